// round 15
// baseline (speedup 1.0000x reference)
#include <cuda_runtime.h>
#include <cuda_bf16.h>
#include <math.h>
#include <stdint.h>

// ---------------- problem constants ----------------
#define BATCH     2
#define SEQ       2048
#define TTOT      (BATCH*SEQ)        // 4096
#define DMODEL    1024
#define DINNER    2048
#define DHEAD     64
#define NHEADS    32
#define DSTATE    64
#define DCONV     4
#define CONVDIM   (DINNER + 2*DSTATE)            // 2176
#define DINPROJ   (2*DINNER + 2*DSTATE + NHEADS) // 4256
#define NLAYERS   4
#define EPSV      1e-5f

#define CHL       128
#define NCH       (SEQ/CHL)
#define TT        16
#define NTILES    (CHL/TT)

// ---------------- scratch ----------------
__device__ float g_zxbcdt[(size_t)TTOT * DINPROJ];
__device__ float g_xconv[(size_t)TTOT * CONVDIM];
__device__ float g_y[(size_t)TTOT * DINNER];
__device__ __nv_bfloat16 g_asp[(size_t)TTOT * 2 * DINNER];
__device__ __nv_bfloat16 g_bw_in [(size_t)NLAYERS * DINPROJ * 2 * DMODEL];
__device__ __nv_bfloat16 g_bw_out[(size_t)NLAYERS * DMODEL * 2 * DINNER];
__device__ float g_Sloc[(size_t)BATCH*NHEADS*NCH * DHEAD * DSTATE];
__device__ float g_Sin [(size_t)BATCH*NHEADS*NCH * DHEAD * DSTATE];
__device__ float g_cumdt[(size_t)TTOT * NHEADS];

__device__ __forceinline__ uint32_t s2u(const void* p) {
    return (uint32_t)__cvta_generic_to_shared(p);
}
__device__ __forceinline__ float softplusf(float v) {
    return (v > 20.f) ? v : log1pf(__expf(v));
}

// ========== HL-fused bf16 GEMM: C = A32 @ B32^T via split-bf16 ==========
// Storage: A row = [hi(K)|lo(K)], B row = [hi(K)|lo(K)], stride 2K.
// Per k-step (32): load Ahi,Alo,Bhi,Blo tiles; acc += Ahi*Bhi + Alo*Bhi + Ahi*Blo.
// CTA 128x128, 8 warps (2x4), warp tile 64x32. 6-slot ring of 16KB slots.
#define BM 128
#define BN 128
#define BKH 32                        // k elems per step
#define SLOT_A 8192                   // A tile: 128 rows x 64B
#define SLOT_BYTES 16384              // [A|B]
#define GEMM_SMEM_BYTES (6 * SLOT_BYTES)   // 98304

// load one (A,B) tile pair for k-offset koff (element offset within 2K row)
__device__ __forceinline__ void gemm_issue_hl(
    const __nv_bfloat16* __restrict__ A, const __nv_bfloat16* __restrict__ B,
    int N, int K2, int m0, int n0, int koff, char* slot, int tid)
{
    // A: 512 chunks of 16B, B: 512 chunks; 4 per thread
    #pragma unroll
    for (int it = 0; it < 2; it++) {
        int id  = tid + it * 256;      // 0..511
        int row = id >> 2;
        int ch  = id & 3;
        int sw  = ch ^ ((row >> 1) & 3);
        int dst = row * 64 + sw * 16;
        {
            uint32_t saddr = s2u(slot + dst);
            const void* g = A + (size_t)(m0 + row) * K2 + koff + ch * 8;
            asm volatile("cp.async.cg.shared.global [%0], [%1], 16;"
                         :: "r"(saddr), "l"(g));
        }
        {
            uint32_t saddr = s2u(slot + SLOT_A + dst);
            int valid = (n0 + row) < N;
            const void* g = B + (valid ? ((size_t)(n0 + row) * K2 + koff + ch * 8) : 0);
            int sz = valid ? 16 : 0;
            asm volatile("cp.async.cg.shared.global [%0], [%1], 16, %2;"
                         :: "r"(saddr), "l"(g), "r"(sz));
        }
    }
}

#define LDSM_A4(dst, base, rowe, che) do {                                   \
    int _r = (rowe); int _c = (che); int _sw = _c ^ ((_r >> 1) & 3);         \
    uint32_t _ad = s2u((base) + _r * 64 + _sw * 16);                         \
    asm volatile("ldmatrix.sync.aligned.m8n8.x4.shared.b16 {%0,%1,%2,%3}, [%4];" \
                 : "=r"((dst)[0]), "=r"((dst)[1]), "=r"((dst)[2]), "=r"((dst)[3]) \
                 : "r"(_ad)); } while (0)

__global__ __launch_bounds__(256, 2)
void gemm_bf16_nt(const __nv_bfloat16* __restrict__ A, const __nv_bfloat16* __restrict__ B,
                  float* __restrict__ C, int M, int N, int K, int addC)
{
    extern __shared__ __align__(16) char dynsmem[];

    int tid  = threadIdx.x;
    int lane = tid & 31;
    int wid  = tid >> 5;
    int m0 = blockIdx.y * BM;
    int n0 = blockIdx.x * BN;
    int wm = (wid & 1) * 64;
    int wn = (wid >> 1) * 32;
    int K2 = 2 * K;

    float acc[4][4][4];
    #pragma unroll
    for (int a = 0; a < 4; a++)
        #pragma unroll
        for (int b = 0; b < 4; b++)
            #pragma unroll
            for (int c = 0; c < 4; c++) acc[a][b][c] = 0.f;

    int NT = K / BKH;                  // k steps (>= 32 for our shapes)

    // prologue: kin 0 -> slots 0,1 ; kin 1 -> slots 2,3
    gemm_issue_hl(A, B, N, K2, m0, n0, 0,       dynsmem,                  tid);
    gemm_issue_hl(A, B, N, K2, m0, n0, K,       dynsmem + SLOT_BYTES,     tid);
    asm volatile("cp.async.commit_group;" ::: "memory");
    gemm_issue_hl(A, B, N, K2, m0, n0, BKH,     dynsmem + 2 * SLOT_BYTES, tid);
    gemm_issue_hl(A, B, N, K2, m0, n0, K + BKH, dynsmem + 3 * SLOT_BYTES, tid);
    asm volatile("cp.async.commit_group;" ::: "memory");

    int sH = 0;   // slot index of H for current kin (= (2i)%6)
    int sI = 4;   // slot index where kin i+2's H goes (= (2i+4)%6)
    for (int i = 0; i < NT; i++) {
        asm volatile("cp.async.wait_group 1;" ::: "memory");
        __syncthreads();
        if (i + 2 < NT) {
            int kin = (i + 2) * BKH;
            gemm_issue_hl(A, B, N, K2, m0, n0, kin,
                          dynsmem + sI * SLOT_BYTES, tid);
            gemm_issue_hl(A, B, N, K2, m0, n0, K + kin,
                          dynsmem + (sI + 1 == 6 ? 0 : sI + 1) * SLOT_BYTES, tid);
        }
        asm volatile("cp.async.commit_group;" ::: "memory");

        char* hA = dynsmem + sH * SLOT_BYTES;
        char* hB = hA + SLOT_A;
        char* lA = dynsmem + (sH + 1 == 6 ? 0 : sH + 1) * SLOT_BYTES;
        char* lB = lA + SLOT_A;
        sH += 2; if (sH >= 6) sH -= 6;
        sI += 2; if (sI >= 6) sI -= 6;

        #pragma unroll
        for (int ks = 0; ks < 2; ks++) {
            uint32_t aH[4][4], aL[4][4];
            uint32_t bH[4][2], bL[4][2];
            #pragma unroll
            for (int mi = 0; mi < 4; mi++) {
                LDSM_A4(aH[mi], hA, wm + mi * 16 + (lane & 15), ks * 2 + (lane >> 4));
            }
            #pragma unroll
            for (int nj = 0; nj < 4; nj += 2) {
                uint32_t tmp[4];
                LDSM_A4(tmp, hB, wn + nj * 8 + (lane >> 4) * 8 + (lane & 7),
                        ks * 2 + ((lane >> 3) & 1));
                bH[nj][0] = tmp[0]; bH[nj][1] = tmp[1];
                bH[nj + 1][0] = tmp[2]; bH[nj + 1][1] = tmp[3];
            }
            // region 0: aH * bH
            #pragma unroll
            for (int mi = 0; mi < 4; mi++)
                #pragma unroll
                for (int nj = 0; nj < 4; nj++)
                    asm volatile(
                        "mma.sync.aligned.m16n8k16.row.col.f32.bf16.bf16.f32 "
                        "{%0,%1,%2,%3}, {%4,%5,%6,%7}, {%8,%9}, {%0,%1,%2,%3};"
                        : "+f"(acc[mi][nj][0]), "+f"(acc[mi][nj][1]),
                          "+f"(acc[mi][nj][2]), "+f"(acc[mi][nj][3])
                        : "r"(aH[mi][0]), "r"(aH[mi][1]),
                          "r"(aH[mi][2]), "r"(aH[mi][3]),
                          "r"(bH[nj][0]), "r"(bH[nj][1]));
            // region 1: aL * bH
            #pragma unroll
            for (int mi = 0; mi < 4; mi++) {
                LDSM_A4(aL[mi], lA, wm + mi * 16 + (lane & 15), ks * 2 + (lane >> 4));
            }
            #pragma unroll
            for (int mi = 0; mi < 4; mi++)
                #pragma unroll
                for (int nj = 0; nj < 4; nj++)
                    asm volatile(
                        "mma.sync.aligned.m16n8k16.row.col.f32.bf16.bf16.f32 "
                        "{%0,%1,%2,%3}, {%4,%5,%6,%7}, {%8,%9}, {%0,%1,%2,%3};"
                        : "+f"(acc[mi][nj][0]), "+f"(acc[mi][nj][1]),
                          "+f"(acc[mi][nj][2]), "+f"(acc[mi][nj][3])
                        : "r"(aL[mi][0]), "r"(aL[mi][1]),
                          "r"(aL[mi][2]), "r"(aL[mi][3]),
                          "r"(bH[nj][0]), "r"(bH[nj][1]));
            // region 2: aH * bL
            #pragma unroll
            for (int nj = 0; nj < 4; nj += 2) {
                uint32_t tmp[4];
                LDSM_A4(tmp, lB, wn + nj * 8 + (lane >> 4) * 8 + (lane & 7),
                        ks * 2 + ((lane >> 3) & 1));
                bL[nj][0] = tmp[0]; bL[nj][1] = tmp[1];
                bL[nj + 1][0] = tmp[2]; bL[nj + 1][1] = tmp[3];
            }
            #pragma unroll
            for (int mi = 0; mi < 4; mi++)
                #pragma unroll
                for (int nj = 0; nj < 4; nj++)
                    asm volatile(
                        "mma.sync.aligned.m16n8k16.row.col.f32.bf16.bf16.f32 "
                        "{%0,%1,%2,%3}, {%4,%5,%6,%7}, {%8,%9}, {%0,%1,%2,%3};"
                        : "+f"(acc[mi][nj][0]), "+f"(acc[mi][nj][1]),
                          "+f"(acc[mi][nj][2]), "+f"(acc[mi][nj][3])
                        : "r"(aH[mi][0]), "r"(aH[mi][1]),
                          "r"(aH[mi][2]), "r"(aH[mi][3]),
                          "r"(bL[nj][0]), "r"(bL[nj][1]));
        }
    }

    #pragma unroll
    for (int mi = 0; mi < 4; mi++) {
        int r0 = m0 + wm + mi * 16 + (lane >> 2);
        #pragma unroll
        for (int nj = 0; nj < 4; nj++) {
            int c0 = n0 + wn + nj * 8 + (lane & 3) * 2;
            if (c0 < N) {
                float2* p0 = (float2*)(C + (size_t)r0 * N + c0);
                float2* p1 = (float2*)(C + (size_t)(r0 + 8) * N + c0);
                float2 v0 = make_float2(acc[mi][nj][0], acc[mi][nj][1]);
                float2 v1 = make_float2(acc[mi][nj][2], acc[mi][nj][3]);
                if (addC) {
                    float2 o0 = *p0, o1 = *p1;
                    v0.x += o0.x; v0.y += o0.y;
                    v1.x += o1.x; v1.y += o1.y;
                }
                *p0 = v0;
                *p1 = v1;
            }
        }
    }
}

// ---------------- rmsnorm + [hi|lo] split, float4 ----------------
__global__ void rmsnorm_split_kernel(const float* __restrict__ x,
                                     const float* __restrict__ w,
                                     __nv_bfloat16* __restrict__ O)
{
    int t = blockIdx.x;
    int tid = threadIdx.x;
    const float4* xr4 = (const float4*)(x + (size_t)t * DMODEL);
    float4 v = xr4[tid];
    float lsum = v.x * v.x + v.y * v.y + v.z * v.z + v.w * v.w;

    __shared__ float wsum[8];
    int lane = tid & 31, wid = tid >> 5;
    #pragma unroll
    for (int off = 16; off > 0; off >>= 1)
        lsum += __shfl_xor_sync(0xffffffffu, lsum, off);
    if (lane == 0) wsum[wid] = lsum;
    __syncthreads();
    __shared__ float s_rs;
    if (tid == 0) {
        float tot = 0.f;
        for (int i = 0; i < 8; i++) tot += wsum[i];
        s_rs = rsqrtf(tot / (float)DMODEL + EPSV);
    }
    __syncthreads();
    float rs = s_rs;
    float4 wv = ((const float4*)w)[tid];
    float o[4] = {v.x * rs * wv.x, v.y * rs * wv.y, v.z * rs * wv.z, v.w * rs * wv.w};
    __nv_bfloat16 hi[4], lo[4];
    #pragma unroll
    for (int j = 0; j < 4; j++) {
        hi[j] = __float2bfloat16(o[j]);
        lo[j] = __float2bfloat16(o[j] - __bfloat162float(hi[j]));
    }
    __nv_bfloat16* orow = O + (size_t)t * (2 * DMODEL) + tid * 4;
    __nv_bfloat162* p0 = (__nv_bfloat162*)orow;
    __nv_bfloat162* p1 = (__nv_bfloat162*)(orow + DMODEL);
    p0[0] = __nv_bfloat162{hi[0], hi[1]};  p0[1] = __nv_bfloat162{hi[2], hi[3]};
    p1[0] = __nv_bfloat162{lo[0], lo[1]};  p1[1] = __nv_bfloat162{lo[2], lo[3]};
}

// ---------------- weight split: fp32 -> [hi | lo], float4 ----------
__global__ void split_w_kernel(const float* __restrict__ X, __nv_bfloat16* __restrict__ O,
                               int rows, int K)
{
    int i4 = blockIdx.x * blockDim.x + threadIdx.x;
    int kq = K >> 2;
    if (i4 >= rows * kq) return;
    int r = i4 / kq;
    int k = (i4 - r * kq) * 4;
    float4 x = ((const float4*)X)[i4];
    float xv[4] = {x.x, x.y, x.z, x.w};
    __nv_bfloat16 hi[4], lo[4];
    #pragma unroll
    for (int j = 0; j < 4; j++) {
        hi[j] = __float2bfloat16(xv[j]);
        lo[j] = __float2bfloat16(xv[j] - __bfloat162float(hi[j]));
    }
    __nv_bfloat16* orow = O + (size_t)r * (2 * K) + k;
    __nv_bfloat162* p0 = (__nv_bfloat162*)orow;
    __nv_bfloat162* p1 = (__nv_bfloat162*)(orow + K);
    p0[0] = __nv_bfloat162{hi[0], hi[1]};  p0[1] = __nv_bfloat162{hi[2], hi[3]};
    p1[0] = __nv_bfloat162{lo[0], lo[1]};  p1[1] = __nv_bfloat162{lo[2], lo[3]};
}

// ---------------- depthwise conv(4) + silu: 4 timesteps per thread ----------
__global__ void conv_silu_kernel(const float* __restrict__ zxbcdt,
                                 const float* __restrict__ cw,
                                 const float* __restrict__ cb,
                                 float* __restrict__ xconv)
{
    const int NC4 = CONVDIM / 4;
    int i = blockIdx.x * blockDim.x + threadIdx.x;
    if (i >= (TTOT / 4) * NC4) return;
    int c4 = i % NC4;
    int tp = i / NC4;
    int b  = tp / (SEQ / 4);
    int l0 = (tp % (SEQ / 4)) * 4;
    int ch = c4 * 4;

    float wk[DCONV][4];
    #pragma unroll
    for (int j = 0; j < 4; j++) {
        float4 w = *(const float4*)(cw + (ch + j) * DCONV);
        wk[0][j] = w.x; wk[1][j] = w.y; wk[2][j] = w.z; wk[3][j] = w.w;
    }
    float4 bb = *(const float4*)(cb + ch);

    float4 in[7];
    #pragma unroll
    for (int k = 0; k < 7; k++) {
        int ll = l0 - 3 + k;
        if (ll >= 0)
            in[k] = *(const float4*)(zxbcdt + (size_t)(b * SEQ + ll) * DINPROJ + DINNER + ch);
        else
            in[k] = make_float4(0.f, 0.f, 0.f, 0.f);
    }

    #pragma unroll
    for (int o = 0; o < 4; o++) {
        float a[4] = {bb.x, bb.y, bb.z, bb.w};
        #pragma unroll
        for (int k = 0; k < DCONV; k++) {
            float* vp = (float*)&in[o + k];
            #pragma unroll
            for (int j = 0; j < 4; j++)
                a[j] = fmaf(vp[j], wk[k][j], a[j]);
        }
        float4 ov;
        ov.x = a[0] / (1.f + __expf(-a[0]));
        ov.y = a[1] / (1.f + __expf(-a[1]));
        ov.z = a[2] / (1.f + __expf(-a[2]));
        ov.w = a[3] / (1.f + __expf(-a[3]));
        *(float4*)(xconv + (size_t)(b * SEQ + l0 + o) * CONVDIM + ch) = ov;
    }
}

// ---------------- SSD phase A: fused dt + triple-buffered local scan --------
__device__ __forceinline__ void ssd_local_issue(
    const float* __restrict__ xconv, const float* __restrict__ zxbcdt,
    int tbase, int t0, int h,
    float* sBC, float* sX, float* sdtraw, int tid)
{
    #pragma unroll
    for (int it = 0; it < 2; it++) {
        int id = tid + it * 256;
        int w = id >> 5, ch = id & 31;
        const void* g = xconv + (size_t)(tbase + t0 + w) * CONVDIM + DINNER + ch * 4;
        asm volatile("cp.async.cg.shared.global [%0], [%1], 16;"
                     :: "r"(s2u(sBC + w * 128 + ch * 4)), "l"(g));
    }
    {
        int w = tid >> 4, ch = tid & 15;
        const void* g = xconv + (size_t)(tbase + t0 + w) * CONVDIM + h * DHEAD + ch * 4;
        asm volatile("cp.async.cg.shared.global [%0], [%1], 16;"
                     :: "r"(s2u(sX + w * 64 + ch * 4)), "l"(g));
    }
    if (tid < TT) {
        const void* g = zxbcdt + (size_t)(tbase + t0 + tid) * DINPROJ
                        + (DINPROJ - NHEADS) + h;
        asm volatile("cp.async.ca.shared.global [%0], [%1], 4;"
                     :: "r"(s2u(sdtraw + tid)), "l"(g));
    }
}

__global__ __launch_bounds__(256, 4)
void ssd_local_kernel(const float* __restrict__ xconv,
                      const float* __restrict__ zxbcdt,
                      const float* __restrict__ dt_bias,
                      const float* __restrict__ A_log,
                      const float* __restrict__ Dvec,
                      float* __restrict__ y,
                      float* __restrict__ Sloc,
                      float* __restrict__ cumdt)
{
    int bhc = blockIdx.x;
    int c = bhc & (NCH - 1);
    int h = (bhc >> 4) & 31;
    int b = bhc >> 9;
    float A    = -__expf(A_log[h]);
    float Dh   = Dvec[h];
    float bias = dt_bias[h];
    int tid  = threadIdx.x;
    int p    = tid >> 2;
    int quad = tid & 3;
    int q4   = quad * 4;

    __shared__ float sBC[3][TT][128];
    __shared__ float sX[3][TT][DHEAD];
    __shared__ float sdtraw[3][TT];

    float s[16];
    #pragma unroll
    for (int j = 0; j < 16; j++) s[j] = 0.f;
    float cum = 0.f;
    int tbase = b * SEQ + c * CHL;

    ssd_local_issue(xconv, zxbcdt, tbase, 0, h,
                    &sBC[0][0][0], &sX[0][0][0], sdtraw[0], tid);
    asm volatile("cp.async.commit_group;" ::: "memory");

    for (int i = 0; i < NTILES; i++) {
        if (i + 1 < NTILES) {
            int nb = (i + 1) % 3;
            ssd_local_issue(xconv, zxbcdt, tbase, (i + 1) * TT, h,
                            &sBC[nb][0][0], &sX[nb][0][0], sdtraw[nb], tid);
        }
        asm volatile("cp.async.commit_group;" ::: "memory");
        asm volatile("cp.async.wait_group 1;" ::: "memory");
        __syncthreads();

        int bf = i % 3;
        if (tid == 0) {
            float cc = cum;
            #pragma unroll
            for (int w = 0; w < TT; w++) {
                cc += softplusf(sdtraw[bf][w] + bias);
                cumdt[(size_t)(tbase + i * TT + w) * NHEADS + h] = cc;
            }
            cum = cc;
        }

        #pragma unroll
        for (int w = 0; w < TT; w++) {
            float dts = softplusf(sdtraw[bf][w] + bias);
            float da  = __expf(dts * A);
            float xp  = sX[bf][w][p] * dts;
            float accv = 0.f;
            #pragma unroll
            for (int j4 = 0; j4 < 4; j4++) {
                float4 bv = *(const float4*)&sBC[bf][w][q4 + j4 * 16];
                float4 cv = *(const float4*)&sBC[bf][w][64 + q4 + j4 * 16];
                float* bvp = (float*)&bv;
                float* cvp = (float*)&cv;
                #pragma unroll
                for (int jj = 0; jj < 4; jj++) {
                    int idx = j4 * 4 + jj;
                    s[idx] = fmaf(da, s[idx], xp * bvp[jj]);
                    accv   = fmaf(cvp[jj], s[idx], accv);
                }
            }
            accv += __shfl_xor_sync(0xffffffffu, accv, 1);
            accv += __shfl_xor_sync(0xffffffffu, accv, 2);
            if (quad == 0)
                y[(size_t)(tbase + i * TT + w) * DINNER + h * DHEAD + p]
                    = accv + Dh * sX[bf][w][p];
        }
    }

    float* sl = Sloc + ((size_t)bhc * DHEAD + p) * DSTATE + q4;
    #pragma unroll
    for (int j4 = 0; j4 < 4; j4++)
        *(float4*)(sl + j4 * 16) = make_float4(s[j4 * 4], s[j4 * 4 + 1],
                                               s[j4 * 4 + 2], s[j4 * 4 + 3]);
}

// ---------------- SSD phase B ----------------
__global__ void ssd_combine_kernel(const float* __restrict__ Sloc,
                                   const float* __restrict__ cumdt,
                                   const float* __restrict__ A_log,
                                   float* __restrict__ Sin)
{
    int bh = blockIdx.x;
    int b = bh >> 5, h = bh & 31;
    float A = -__expf(A_log[h]);
    int tid = threadIdx.x;
    int p = tid >> 2, quad = tid & 3;
    int q4 = quad * 4;

    float4 s[4];
    #pragma unroll
    for (int j4 = 0; j4 < 4; j4++) s[j4] = make_float4(0.f, 0.f, 0.f, 0.f);

    for (int c = 0; c < NCH; c++) {
        size_t base = (((size_t)(b * 512 + h * 16 + c)) * DHEAD + p) * DSTATE + q4;
        float dec = __expf(A * cumdt[(size_t)(b * SEQ + c * CHL + CHL - 1) * NHEADS + h]);
        #pragma unroll
        for (int j4 = 0; j4 < 4; j4++) {
            float4 sl = *(const float4*)(Sloc + base + j4 * 16);
            *(float4*)(Sin + base + j4 * 16) = s[j4];
            s[j4].x = fmaf(dec, s[j4].x, sl.x);
            s[j4].y = fmaf(dec, s[j4].y, sl.y);
            s[j4].z = fmaf(dec, s[j4].z, sl.z);
            s[j4].w = fmaf(dec, s[j4].w, sl.w);
        }
    }
}

// ---------------- SSD phase C ----------------
__device__ __forceinline__ void ssd_corr_issue(
    const float* __restrict__ xconv, const float* __restrict__ cumdt,
    int tbase, int t0, int h, float* sC, float* scum, int tid)
{
    {
        int w = tid >> 4, ch = tid & 15;
        const void* g = xconv + (size_t)(tbase + t0 + w) * CONVDIM
                        + DINNER + DSTATE + ch * 4;
        asm volatile("cp.async.cg.shared.global [%0], [%1], 16;"
                     :: "r"(s2u(sC + w * 64 + ch * 4)), "l"(g));
    }
    if (tid < TT) {
        const void* g = cumdt + (size_t)(tbase + t0 + tid) * NHEADS + h;
        asm volatile("cp.async.ca.shared.global [%0], [%1], 4;"
                     :: "r"(s2u(scum + tid)), "l"(g));
    }
}

__global__ __launch_bounds__(256, 4)
void ssd_correct_kernel(const float* __restrict__ xconv,
                        const float* __restrict__ cumdt,
                        const float* __restrict__ A_log,
                        const float* __restrict__ Sin,
                        float* __restrict__ y)
{
    int bhc = blockIdx.x;
    int c = bhc & (NCH - 1);
    if (c == 0) return;
    int h = (bhc >> 4) & 31;
    int b = bhc >> 9;
    float A = -__expf(A_log[h]);
    int tid = threadIdx.x;
    int p = tid >> 2, quad = tid & 3;
    int q4 = quad * 4;

    float sin[16];
    {
        const float* sp = Sin + ((size_t)bhc * DHEAD + p) * DSTATE + q4;
        #pragma unroll
        for (int j4 = 0; j4 < 4; j4++) {
            float4 v = *(const float4*)(sp + j4 * 16);
            sin[j4 * 4]     = v.x;
            sin[j4 * 4 + 1] = v.y;
            sin[j4 * 4 + 2] = v.z;
            sin[j4 * 4 + 3] = v.w;
        }
    }

    __shared__ float sC[3][TT][DSTATE];
    __shared__ float scum[3][TT];
    int tbase = b * SEQ + c * CHL;

    ssd_corr_issue(xconv, cumdt, tbase, 0, h, &sC[0][0][0], scum[0], tid);
    asm volatile("cp.async.commit_group;" ::: "memory");

    for (int i = 0; i < NTILES; i++) {
        if (i + 1 < NTILES) {
            int nb = (i + 1) % 3;
            ssd_corr_issue(xconv, cumdt, tbase, (i + 1) * TT, h,
                           &sC[nb][0][0], scum[nb], tid);
        }
        asm volatile("cp.async.commit_group;" ::: "memory");
        asm volatile("cp.async.wait_group 1;" ::: "memory");
        __syncthreads();

        int bf = i % 3;
        #pragma unroll
        for (int w = 0; w < TT; w++) {
            float acc = 0.f;
            #pragma unroll
            for (int j4 = 0; j4 < 4; j4++) {
                float4 cv = *(const float4*)&sC[bf][w][q4 + j4 * 16];
                acc = fmaf(cv.x, sin[j4 * 4],     acc);
                acc = fmaf(cv.y, sin[j4 * 4 + 1], acc);
                acc = fmaf(cv.z, sin[j4 * 4 + 2], acc);
                acc = fmaf(cv.w, sin[j4 * 4 + 3], acc);
            }
            acc += __shfl_xor_sync(0xffffffffu, acc, 1);
            acc += __shfl_xor_sync(0xffffffffu, acc, 2);
            if (quad == 0) {
                float wgt = __expf(A * scum[bf][w]);
                y[(size_t)(tbase + i * TT + w) * DINNER + h * DHEAD + p] += wgt * acc;
            }
        }
    }
}

// ---------------- gate + rmsnorm + [hi|lo] split ----------------
__global__ void gate_norm_split_kernel(const float* __restrict__ zxbcdt,
                                       const float* __restrict__ y,
                                       const float* __restrict__ gw,
                                       __nv_bfloat16* __restrict__ O)
{
    int t = blockIdx.x;
    int tid = threadIdx.x;
    __shared__ float sv[DINNER];
    __shared__ float wsum[8];
    const float4* zr = (const float4*)(zxbcdt + (size_t)t * DINPROJ);
    const float4* yr = (const float4*)(y + (size_t)t * DINNER);
    float lsum = 0.f;
    #pragma unroll
    for (int it = 0; it < 2; it++) {
        int i4 = tid + it * 256;
        float4 z = zr[i4];
        float4 yv = yr[i4];
        float4 v;
        v.x = yv.x * (z.x / (1.f + __expf(-z.x)));
        v.y = yv.y * (z.y / (1.f + __expf(-z.y)));
        v.z = yv.z * (z.z / (1.f + __expf(-z.z)));
        v.w = yv.w * (z.w / (1.f + __expf(-z.w)));
        ((float4*)sv)[i4] = v;
        lsum += v.x * v.x + v.y * v.y + v.z * v.z + v.w * v.w;
    }
    int lane = tid & 31, wid = tid >> 5;
    #pragma unroll
    for (int off = 16; off > 0; off >>= 1)
        lsum += __shfl_xor_sync(0xffffffffu, lsum, off);
    if (lane == 0) wsum[wid] = lsum;
    __syncthreads();
    __shared__ float s_rs;
    if (tid == 0) {
        float tot = 0.f;
        for (int i = 0; i < 8; i++) tot += wsum[i];
        s_rs = rsqrtf(tot / (float)DINNER + EPSV);
    }
    __syncthreads();
    float rs = s_rs;
    __nv_bfloat16* obase = O + (size_t)t * (2 * DINNER);
    #pragma unroll
    for (int it = 0; it < 2; it++) {
        int i4 = tid + it * 256;
        float4 v = ((float4*)sv)[i4];
        float4 wv = ((const float4*)gw)[i4];
        float o[4] = {v.x * rs * wv.x, v.y * rs * wv.y, v.z * rs * wv.z, v.w * rs * wv.w};
        __nv_bfloat16 hi[4], lo[4];
        #pragma unroll
        for (int j = 0; j < 4; j++) {
            hi[j] = __float2bfloat16(o[j]);
            lo[j] = __float2bfloat16(o[j] - __bfloat162float(hi[j]));
        }
        __nv_bfloat16* orow = obase + i4 * 4;
        __nv_bfloat162* p0 = (__nv_bfloat162*)orow;
        __nv_bfloat162* p1 = (__nv_bfloat162*)(orow + DINNER);
        p0[0] = __nv_bfloat162{hi[0], hi[1]};  p0[1] = __nv_bfloat162{hi[2], hi[3]};
        p1[0] = __nv_bfloat162{lo[0], lo[1]};  p1[1] = __nv_bfloat162{lo[2], lo[3]};
    }
}

// ---------------- host orchestration ----------------
extern "C" void kernel_launch(void* const* d_in, const int* in_sizes, int n_in,
                              void* d_out, int out_size)
{
    const float* x        = (const float*)d_in[0];
    const float* in_w     = (const float*)d_in[1];
    const float* conv_w   = (const float*)d_in[2];
    const float* conv_b   = (const float*)d_in[3];
    const float* dt_bias  = (const float*)d_in[4];
    const float* A_log    = (const float*)d_in[5];
    const float* Dvec     = (const float*)d_in[6];
    const float* gnorm_w  = (const float*)d_in[7];
    const float* out_w    = (const float*)d_in[8];
    const float* rms_w    = (const float*)d_in[9];
    float* out = (float*)d_out;

    float *p_zx, *p_xc, *p_y, *p_sl, *p_si, *p_cd;
    __nv_bfloat16 *p_as, *p_bwin, *p_bwout;
    cudaGetSymbolAddress((void**)&p_zx, g_zxbcdt);
    cudaGetSymbolAddress((void**)&p_xc, g_xconv);
    cudaGetSymbolAddress((void**)&p_y,  g_y);
    cudaGetSymbolAddress((void**)&p_sl, g_Sloc);
    cudaGetSymbolAddress((void**)&p_si, g_Sin);
    cudaGetSymbolAddress((void**)&p_cd, g_cumdt);
    cudaGetSymbolAddress((void**)&p_as, g_asp);
    cudaGetSymbolAddress((void**)&p_bwin,  g_bw_in);
    cudaGetSymbolAddress((void**)&p_bwout, g_bw_out);

    cudaFuncSetAttribute(gemm_bf16_nt,
                         cudaFuncAttributeMaxDynamicSharedMemorySize, GEMM_SMEM_BYTES);

    cudaMemcpyAsync(out, x, (size_t)TTOT * DMODEL * sizeof(float),
                    cudaMemcpyDeviceToDevice);

    split_w_kernel<<<((size_t)NLAYERS * DINPROJ * DMODEL / 4 + 255) / 256, 256>>>(
        in_w, p_bwin, NLAYERS * DINPROJ, DMODEL);
    split_w_kernel<<<((size_t)NLAYERS * DMODEL * DINNER / 4 + 255) / 256, 256>>>(
        out_w, p_bwout, NLAYERS * DMODEL, DINNER);

    for (int layer = 0; layer < NLAYERS; layer++) {
        const __nv_bfloat16* lw_in_t  = p_bwin  + (size_t)layer * DINPROJ * 2 * DMODEL;
        const __nv_bfloat16* lw_out_t = p_bwout + (size_t)layer * DMODEL * 2 * DINNER;
        const float* lw_cw   = conv_w  + (size_t)layer * CONVDIM * DCONV;
        const float* lw_cb   = conv_b  + (size_t)layer * CONVDIM;
        const float* lw_dtb  = dt_bias + (size_t)layer * NHEADS;
        const float* lw_Alog = A_log   + (size_t)layer * NHEADS;
        const float* lw_D    = Dvec    + (size_t)layer * NHEADS;
        const float* lw_gn   = gnorm_w + (size_t)layer * DINNER;
        const float* lw_rms  = rms_w   + (size_t)layer * DMODEL;

        rmsnorm_split_kernel<<<TTOT, 256>>>(out, lw_rms, p_as);

        {
            dim3 grid((DINPROJ + BN - 1) / BN, TTOT / BM);
            gemm_bf16_nt<<<grid, 256, GEMM_SMEM_BYTES>>>(p_as, lw_in_t, p_zx,
                                                         TTOT, DINPROJ, DMODEL, 0);
        }

        {
            int total = (TTOT / 4) * (CONVDIM / 4);
            conv_silu_kernel<<<(total + 255) / 256, 256>>>(p_zx, lw_cw, lw_cb, p_xc);
        }

        ssd_local_kernel<<<BATCH * NHEADS * NCH, 256>>>(p_xc, p_zx, lw_dtb,
                                                        lw_Alog, lw_D,
                                                        p_y, p_sl, p_cd);
        ssd_combine_kernel<<<BATCH * NHEADS, 256>>>(p_sl, p_cd, lw_Alog, p_si);
        ssd_correct_kernel<<<BATCH * NHEADS * NCH, 256>>>(p_xc, p_cd, lw_Alog, p_si, p_y);

        gate_norm_split_kernel<<<TTOT, 256>>>(p_zx, p_y, lw_gn, p_as);

        {
            dim3 grid(DMODEL / BN, TTOT / BM);
            gemm_bf16_nt<<<grid, 256, GEMM_SMEM_BYTES>>>(p_as, lw_out_t, out,
                                                         TTOT, DMODEL, DINNER, 1);
        }
    }
}

// round 16
// speedup vs baseline: 1.0287x; 1.0287x over previous
#include <cuda_runtime.h>
#include <cuda_bf16.h>
#include <math.h>
#include <stdint.h>

// ---------------- problem constants ----------------
#define BATCH     2
#define SEQ       2048
#define TTOT      (BATCH*SEQ)        // 4096
#define DMODEL    1024
#define DINNER    2048
#define DHEAD     64
#define NHEADS    32
#define DSTATE    64
#define DCONV     4
#define CONVDIM   (DINNER + 2*DSTATE)            // 2176
#define DINPROJ   (2*DINNER + 2*DSTATE + NHEADS) // 4256
#define NLAYERS   4
#define EPSV      1e-5f

#define CHL       128
#define NCH       (SEQ/CHL)
#define TT        16
#define NTILES    (CHL/TT)

// ---------------- scratch ----------------
__device__ float g_zxbcdt[(size_t)TTOT * DINPROJ];
__device__ float g_xconv[(size_t)TTOT * CONVDIM];
__device__ float g_y[(size_t)TTOT * DINNER];
__device__ __nv_bfloat16 g_asp[(size_t)TTOT * 2 * DINNER];
__device__ __nv_bfloat16 g_bw_in [(size_t)NLAYERS * DINPROJ * 2 * DMODEL];
__device__ __nv_bfloat16 g_bw_out[(size_t)NLAYERS * DMODEL * 2 * DINNER];
__device__ float g_Sloc[(size_t)BATCH*NHEADS*NCH * DHEAD * DSTATE];
__device__ float g_Sin [(size_t)BATCH*NHEADS*NCH * DHEAD * DSTATE];
__device__ float g_cumdt[(size_t)TTOT * NHEADS];

__device__ __forceinline__ uint32_t s2u(const void* p) {
    return (uint32_t)__cvta_generic_to_shared(p);
}
__device__ __forceinline__ float softplusf(float v) {
    return (v > 20.f) ? v : log1pf(__expf(v));
}

// =========== bf16 mma.sync NT GEMM: logical K' = 3K over [hi|lo] storage ====
// logical regions: 0 = Ahi*Bhi, 1 = Alo*Bhi, 2 = Ahi*Blo.
// storage: A row = [hi(K) | lo(K)], B row = [hi(K) | lo(K)], stride 2K.
// CTA tile 128x128, 8 warps (2x4), warp tile 64x32, BK=64, 3-stage cp.async.
#define BM 128
#define BN 128
#define BK 64
#define NSTG 3
#define STG_A 16384
#define STG_BYTES (2*STG_A)
#define GEMM_SMEM_BYTES (NSTG * STG_BYTES)   // 98304 B

__device__ __forceinline__ void gemm_issue(
    const __nv_bfloat16* __restrict__ A, const __nv_bfloat16* __restrict__ B,
    int N, int K, int m0, int n0, int kbase,
    char* As, char* Bs, int tid)
{
    int offA = (kbase >= 2 * K) ? (kbase - 2 * K) : kbase;   // hi,lo,hi
    int offB = (kbase >= K)     ? (kbase - K)     : kbase;   // hi,hi,lo
    int K2 = 2 * K;
    #pragma unroll
    for (int it = 0; it < 4; it++) {
        int id  = tid + it * 256;
        int row = id >> 3;
        int ch  = id & 7;
        int sw  = ch ^ (row & 7);
        int dst = row * 128 + sw * 16;
        {
            uint32_t saddr = s2u(As + dst);
            const void* g = A + (size_t)(m0 + row) * K2 + offA + ch * 8;
            asm volatile("cp.async.cg.shared.global [%0], [%1], 16;"
                         :: "r"(saddr), "l"(g));
        }
        {
            uint32_t saddr = s2u(Bs + dst);
            int valid = (n0 + row) < N;
            const void* g = B + (valid ? ((size_t)(n0 + row) * K2 + offB + ch * 8) : 0);
            int sz = valid ? 16 : 0;
            asm volatile("cp.async.cg.shared.global [%0], [%1], 16, %2;"
                         :: "r"(saddr), "l"(g), "r"(sz));
        }
    }
}

__global__ __launch_bounds__(256, 2)
void gemm_bf16_nt(const __nv_bfloat16* __restrict__ A, const __nv_bfloat16* __restrict__ B,
                  float* __restrict__ C, int M, int N, int K, int addC)
{
    extern __shared__ __align__(16) char dynsmem[];

    int tid  = threadIdx.x;
    int lane = tid & 31;
    int wid  = tid >> 5;
    int m0 = blockIdx.y * BM;
    int n0 = blockIdx.x * BN;
    int wm = (wid & 1) * 64;
    int wn = (wid >> 1) * 32;

    float acc[4][4][4];
    #pragma unroll
    for (int a = 0; a < 4; a++)
        #pragma unroll
        for (int b = 0; b < 4; b++)
            #pragma unroll
            for (int c = 0; c < 4; c++) acc[a][b][c] = 0.f;

    int NT = (3 * K) / BK;

    #pragma unroll
    for (int s = 0; s < NSTG - 1; s++) {
        gemm_issue(A, B, N, K, m0, n0, s * BK,
                   dynsmem + s * STG_BYTES, dynsmem + s * STG_BYTES + STG_A, tid);
        asm volatile("cp.async.commit_group;" ::: "memory");
    }

    int sc = 0;
    int si = NSTG - 1;
    for (int kt = 0; kt < NT; kt++) {
        asm volatile("cp.async.wait_group 1;" ::: "memory");
        __syncthreads();
        if (kt + 2 < NT) {
            gemm_issue(A, B, N, K, m0, n0, (kt + 2) * BK,
                       dynsmem + si * STG_BYTES, dynsmem + si * STG_BYTES + STG_A, tid);
        }
        asm volatile("cp.async.commit_group;" ::: "memory");
        si = (si == NSTG - 1) ? 0 : si + 1;

        char* As = dynsmem + sc * STG_BYTES;
        char* Bs = As + STG_A;
        sc = (sc == NSTG - 1) ? 0 : sc + 1;

        #pragma unroll
        for (int ks = 0; ks < 4; ks++) {
            uint32_t af[4][4];
            uint32_t bf[4][2];
            #pragma unroll
            for (int mi = 0; mi < 4; mi++) {
                int row = wm + mi * 16 + (lane & 15);
                int ch  = ks * 2 + (lane >> 4);
                int sw  = ch ^ (row & 7);
                uint32_t addr = s2u(As + row * 128 + sw * 16);
                asm volatile("ldmatrix.sync.aligned.m8n8.x4.shared.b16 {%0,%1,%2,%3}, [%4];"
                             : "=r"(af[mi][0]), "=r"(af[mi][1]),
                               "=r"(af[mi][2]), "=r"(af[mi][3])
                             : "r"(addr));
            }
            #pragma unroll
            for (int nj = 0; nj < 4; nj += 2) {
                int row = wn + nj * 8 + (lane >> 4) * 8 + (lane & 7);
                int ch  = ks * 2 + ((lane >> 3) & 1);
                int sw  = ch ^ (row & 7);
                uint32_t addr = s2u(Bs + row * 128 + sw * 16);
                asm volatile("ldmatrix.sync.aligned.m8n8.x4.shared.b16 {%0,%1,%2,%3}, [%4];"
                             : "=r"(bf[nj][0]), "=r"(bf[nj][1]),
                               "=r"(bf[nj + 1][0]), "=r"(bf[nj + 1][1])
                             : "r"(addr));
            }
            #pragma unroll
            for (int mi = 0; mi < 4; mi++)
                #pragma unroll
                for (int nj = 0; nj < 4; nj++)
                    asm volatile(
                        "mma.sync.aligned.m16n8k16.row.col.f32.bf16.bf16.f32 "
                        "{%0,%1,%2,%3}, {%4,%5,%6,%7}, {%8,%9}, {%0,%1,%2,%3};"
                        : "+f"(acc[mi][nj][0]), "+f"(acc[mi][nj][1]),
                          "+f"(acc[mi][nj][2]), "+f"(acc[mi][nj][3])
                        : "r"(af[mi][0]), "r"(af[mi][1]),
                          "r"(af[mi][2]), "r"(af[mi][3]),
                          "r"(bf[nj][0]), "r"(bf[nj][1]));
        }
    }

    #pragma unroll
    for (int mi = 0; mi < 4; mi++) {
        int r0 = m0 + wm + mi * 16 + (lane >> 2);
        #pragma unroll
        for (int nj = 0; nj < 4; nj++) {
            int c0 = n0 + wn + nj * 8 + (lane & 3) * 2;
            if (c0 < N) {
                float2* p0 = (float2*)(C + (size_t)r0 * N + c0);
                float2* p1 = (float2*)(C + (size_t)(r0 + 8) * N + c0);
                float2 v0 = make_float2(acc[mi][nj][0], acc[mi][nj][1]);
                float2 v1 = make_float2(acc[mi][nj][2], acc[mi][nj][3]);
                if (addC) {
                    float2 o0 = *p0, o1 = *p1;
                    v0.x += o0.x; v0.y += o0.y;
                    v1.x += o1.x; v1.y += o1.y;
                }
                *p0 = v0;
                *p1 = v1;
            }
        }
    }
}

// ---------------- rmsnorm + [hi|lo] split, float4 ----------------
__global__ void rmsnorm_split_kernel(const float* __restrict__ x,
                                     const float* __restrict__ w,
                                     __nv_bfloat16* __restrict__ O)
{
    int t = blockIdx.x;
    int tid = threadIdx.x;
    const float4* xr4 = (const float4*)(x + (size_t)t * DMODEL);
    float4 v = xr4[tid];
    float lsum = v.x * v.x + v.y * v.y + v.z * v.z + v.w * v.w;

    __shared__ float wsum[8];
    int lane = tid & 31, wid = tid >> 5;
    #pragma unroll
    for (int off = 16; off > 0; off >>= 1)
        lsum += __shfl_xor_sync(0xffffffffu, lsum, off);
    if (lane == 0) wsum[wid] = lsum;
    __syncthreads();
    __shared__ float s_rs;
    if (tid == 0) {
        float tot = 0.f;
        for (int i = 0; i < 8; i++) tot += wsum[i];
        s_rs = rsqrtf(tot / (float)DMODEL + EPSV);
    }
    __syncthreads();
    float rs = s_rs;
    float4 wv = ((const float4*)w)[tid];
    float o[4] = {v.x * rs * wv.x, v.y * rs * wv.y, v.z * rs * wv.z, v.w * rs * wv.w};
    __nv_bfloat16 hi[4], lo[4];
    #pragma unroll
    for (int j = 0; j < 4; j++) {
        hi[j] = __float2bfloat16(o[j]);
        lo[j] = __float2bfloat16(o[j] - __bfloat162float(hi[j]));
    }
    __nv_bfloat16* orow = O + (size_t)t * (2 * DMODEL) + tid * 4;
    __nv_bfloat162* p0 = (__nv_bfloat162*)orow;
    __nv_bfloat162* p1 = (__nv_bfloat162*)(orow + DMODEL);
    p0[0] = __nv_bfloat162{hi[0], hi[1]};  p0[1] = __nv_bfloat162{hi[2], hi[3]};
    p1[0] = __nv_bfloat162{lo[0], lo[1]};  p1[1] = __nv_bfloat162{lo[2], lo[3]};
}

// ---------------- weight split: fp32 -> [hi | lo], float4 ----------
__global__ void split_w_kernel(const float* __restrict__ X, __nv_bfloat16* __restrict__ O,
                               int rows, int K)
{
    int i4 = blockIdx.x * blockDim.x + threadIdx.x;
    int kq = K >> 2;
    if (i4 >= rows * kq) return;
    int r = i4 / kq;
    int k = (i4 - r * kq) * 4;
    float4 x = ((const float4*)X)[i4];
    float xv[4] = {x.x, x.y, x.z, x.w};
    __nv_bfloat16 hi[4], lo[4];
    #pragma unroll
    for (int j = 0; j < 4; j++) {
        hi[j] = __float2bfloat16(xv[j]);
        lo[j] = __float2bfloat16(xv[j] - __bfloat162float(hi[j]));
    }
    __nv_bfloat16* orow = O + (size_t)r * (2 * K) + k;
    __nv_bfloat162* p0 = (__nv_bfloat162*)orow;
    __nv_bfloat162* p1 = (__nv_bfloat162*)(orow + K);
    p0[0] = __nv_bfloat162{hi[0], hi[1]};  p0[1] = __nv_bfloat162{hi[2], hi[3]};
    p1[0] = __nv_bfloat162{lo[0], lo[1]};  p1[1] = __nv_bfloat162{lo[2], lo[3]};
}

// ---------------- depthwise conv(4) + silu: 4 timesteps per thread ----------
__global__ void conv_silu_kernel(const float* __restrict__ zxbcdt,
                                 const float* __restrict__ cw,
                                 const float* __restrict__ cb,
                                 float* __restrict__ xconv)
{
    const int NC4 = CONVDIM / 4;
    int i = blockIdx.x * blockDim.x + threadIdx.x;
    if (i >= (TTOT / 4) * NC4) return;
    int c4 = i % NC4;
    int tp = i / NC4;
    int b  = tp / (SEQ / 4);
    int l0 = (tp % (SEQ / 4)) * 4;
    int ch = c4 * 4;

    float wk[DCONV][4];
    #pragma unroll
    for (int j = 0; j < 4; j++) {
        float4 w = *(const float4*)(cw + (ch + j) * DCONV);
        wk[0][j] = w.x; wk[1][j] = w.y; wk[2][j] = w.z; wk[3][j] = w.w;
    }
    float4 bb = *(const float4*)(cb + ch);

    float4 in[7];
    #pragma unroll
    for (int k = 0; k < 7; k++) {
        int ll = l0 - 3 + k;
        if (ll >= 0)
            in[k] = *(const float4*)(zxbcdt + (size_t)(b * SEQ + ll) * DINPROJ + DINNER + ch);
        else
            in[k] = make_float4(0.f, 0.f, 0.f, 0.f);
    }

    #pragma unroll
    for (int o = 0; o < 4; o++) {
        float a[4] = {bb.x, bb.y, bb.z, bb.w};
        #pragma unroll
        for (int k = 0; k < DCONV; k++) {
            float* vp = (float*)&in[o + k];
            #pragma unroll
            for (int j = 0; j < 4; j++)
                a[j] = fmaf(vp[j], wk[k][j], a[j]);
        }
        float4 ov;
        ov.x = a[0] / (1.f + __expf(-a[0]));
        ov.y = a[1] / (1.f + __expf(-a[1]));
        ov.z = a[2] / (1.f + __expf(-a[2]));
        ov.w = a[3] / (1.f + __expf(-a[3]));
        *(float4*)(xconv + (size_t)(b * SEQ + l0 + o) * CONVDIM + ch) = ov;
    }
}

// ---------------- SSD phase A: fused dt + triple-buffered local scan --------
__device__ __forceinline__ void ssd_local_issue(
    const float* __restrict__ xconv, const float* __restrict__ zxbcdt,
    int tbase, int t0, int h,
    float* sBC, float* sX, float* sdtraw, int tid)
{
    #pragma unroll
    for (int it = 0; it < 2; it++) {
        int id = tid + it * 256;
        int w = id >> 5, ch = id & 31;
        const void* g = xconv + (size_t)(tbase + t0 + w) * CONVDIM + DINNER + ch * 4;
        asm volatile("cp.async.cg.shared.global [%0], [%1], 16;"
                     :: "r"(s2u(sBC + w * 128 + ch * 4)), "l"(g));
    }
    {
        int w = tid >> 4, ch = tid & 15;
        const void* g = xconv + (size_t)(tbase + t0 + w) * CONVDIM + h * DHEAD + ch * 4;
        asm volatile("cp.async.cg.shared.global [%0], [%1], 16;"
                     :: "r"(s2u(sX + w * 64 + ch * 4)), "l"(g));
    }
    if (tid < TT) {
        const void* g = zxbcdt + (size_t)(tbase + t0 + tid) * DINPROJ
                        + (DINPROJ - NHEADS) + h;
        asm volatile("cp.async.ca.shared.global [%0], [%1], 4;"
                     :: "r"(s2u(sdtraw + tid)), "l"(g));
    }
}

__global__ __launch_bounds__(256, 4)
void ssd_local_kernel(const float* __restrict__ xconv,
                      const float* __restrict__ zxbcdt,
                      const float* __restrict__ dt_bias,
                      const float* __restrict__ A_log,
                      const float* __restrict__ Dvec,
                      float* __restrict__ y,
                      float* __restrict__ Sloc,
                      float* __restrict__ cumdt)
{
    int bhc = blockIdx.x;
    int c = bhc & (NCH - 1);
    int h = (bhc >> 4) & 31;
    int b = bhc >> 9;
    float A    = -__expf(A_log[h]);
    float Dh   = Dvec[h];
    float bias = dt_bias[h];
    int tid  = threadIdx.x;
    int p    = tid >> 2;
    int quad = tid & 3;
    int q4   = quad * 4;

    __shared__ float sBC[3][TT][128];
    __shared__ float sX[3][TT][DHEAD];
    __shared__ float sdtraw[3][TT];

    float s[16];
    #pragma unroll
    for (int j = 0; j < 16; j++) s[j] = 0.f;
    float cum = 0.f;
    int tbase = b * SEQ + c * CHL;

    ssd_local_issue(xconv, zxbcdt, tbase, 0, h,
                    &sBC[0][0][0], &sX[0][0][0], sdtraw[0], tid);
    asm volatile("cp.async.commit_group;" ::: "memory");

    for (int i = 0; i < NTILES; i++) {
        if (i + 1 < NTILES) {
            int nb = (i + 1) % 3;
            ssd_local_issue(xconv, zxbcdt, tbase, (i + 1) * TT, h,
                            &sBC[nb][0][0], &sX[nb][0][0], sdtraw[nb], tid);
        }
        asm volatile("cp.async.commit_group;" ::: "memory");
        asm volatile("cp.async.wait_group 1;" ::: "memory");
        __syncthreads();

        int bf = i % 3;
        if (tid == 0) {
            float cc = cum;
            #pragma unroll
            for (int w = 0; w < TT; w++) {
                cc += softplusf(sdtraw[bf][w] + bias);
                cumdt[(size_t)(tbase + i * TT + w) * NHEADS + h] = cc;
            }
            cum = cc;
        }

        #pragma unroll
        for (int w = 0; w < TT; w++) {
            float dts = softplusf(sdtraw[bf][w] + bias);
            float da  = __expf(dts * A);
            float xp  = sX[bf][w][p] * dts;
            float accv = 0.f;
            #pragma unroll
            for (int j4 = 0; j4 < 4; j4++) {
                float4 bv = *(const float4*)&sBC[bf][w][q4 + j4 * 16];
                float4 cv = *(const float4*)&sBC[bf][w][64 + q4 + j4 * 16];
                float* bvp = (float*)&bv;
                float* cvp = (float*)&cv;
                #pragma unroll
                for (int jj = 0; jj < 4; jj++) {
                    int idx = j4 * 4 + jj;
                    s[idx] = fmaf(da, s[idx], xp * bvp[jj]);
                    accv   = fmaf(cvp[jj], s[idx], accv);
                }
            }
            accv += __shfl_xor_sync(0xffffffffu, accv, 1);
            accv += __shfl_xor_sync(0xffffffffu, accv, 2);
            if (quad == 0)
                y[(size_t)(tbase + i * TT + w) * DINNER + h * DHEAD + p]
                    = accv + Dh * sX[bf][w][p];
        }
    }

    float* sl = Sloc + ((size_t)bhc * DHEAD + p) * DSTATE + q4;
    #pragma unroll
    for (int j4 = 0; j4 < 4; j4++)
        *(float4*)(sl + j4 * 16) = make_float4(s[j4 * 4], s[j4 * 4 + 1],
                                               s[j4 * 4 + 2], s[j4 * 4 + 3]);
}

// ---------------- SSD phase B ----------------
__global__ void ssd_combine_kernel(const float* __restrict__ Sloc,
                                   const float* __restrict__ cumdt,
                                   const float* __restrict__ A_log,
                                   float* __restrict__ Sin)
{
    int bh = blockIdx.x;
    int b = bh >> 5, h = bh & 31;
    float A = -__expf(A_log[h]);
    int tid = threadIdx.x;
    int p = tid >> 2, quad = tid & 3;
    int q4 = quad * 4;

    float4 s[4];
    #pragma unroll
    for (int j4 = 0; j4 < 4; j4++) s[j4] = make_float4(0.f, 0.f, 0.f, 0.f);

    for (int c = 0; c < NCH; c++) {
        size_t base = (((size_t)(b * 512 + h * 16 + c)) * DHEAD + p) * DSTATE + q4;
        float dec = __expf(A * cumdt[(size_t)(b * SEQ + c * CHL + CHL - 1) * NHEADS + h]);
        #pragma unroll
        for (int j4 = 0; j4 < 4; j4++) {
            float4 sl = *(const float4*)(Sloc + base + j4 * 16);
            *(float4*)(Sin + base + j4 * 16) = s[j4];
            s[j4].x = fmaf(dec, s[j4].x, sl.x);
            s[j4].y = fmaf(dec, s[j4].y, sl.y);
            s[j4].z = fmaf(dec, s[j4].z, sl.z);
            s[j4].w = fmaf(dec, s[j4].w, sl.w);
        }
    }
}

// ---------------- SSD phase C ----------------
__device__ __forceinline__ void ssd_corr_issue(
    const float* __restrict__ xconv, const float* __restrict__ cumdt,
    int tbase, int t0, int h, float* sC, float* scum, int tid)
{
    {
        int w = tid >> 4, ch = tid & 15;
        const void* g = xconv + (size_t)(tbase + t0 + w) * CONVDIM
                        + DINNER + DSTATE + ch * 4;
        asm volatile("cp.async.cg.shared.global [%0], [%1], 16;"
                     :: "r"(s2u(sC + w * 64 + ch * 4)), "l"(g));
    }
    if (tid < TT) {
        const void* g = cumdt + (size_t)(tbase + t0 + tid) * NHEADS + h;
        asm volatile("cp.async.ca.shared.global [%0], [%1], 4;"
                     :: "r"(s2u(scum + tid)), "l"(g));
    }
}

__global__ __launch_bounds__(256, 4)
void ssd_correct_kernel(const float* __restrict__ xconv,
                        const float* __restrict__ cumdt,
                        const float* __restrict__ A_log,
                        const float* __restrict__ Sin,
                        float* __restrict__ y)
{
    int bhc = blockIdx.x;
    int c = bhc & (NCH - 1);
    if (c == 0) return;
    int h = (bhc >> 4) & 31;
    int b = bhc >> 9;
    float A = -__expf(A_log[h]);
    int tid = threadIdx.x;
    int p = tid >> 2, quad = tid & 3;
    int q4 = quad * 4;

    float sin[16];
    {
        const float* sp = Sin + ((size_t)bhc * DHEAD + p) * DSTATE + q4;
        #pragma unroll
        for (int j4 = 0; j4 < 4; j4++) {
            float4 v = *(const float4*)(sp + j4 * 16);
            sin[j4 * 4]     = v.x;
            sin[j4 * 4 + 1] = v.y;
            sin[j4 * 4 + 2] = v.z;
            sin[j4 * 4 + 3] = v.w;
        }
    }

    __shared__ float sC[3][TT][DSTATE];
    __shared__ float scum[3][TT];
    int tbase = b * SEQ + c * CHL;

    ssd_corr_issue(xconv, cumdt, tbase, 0, h, &sC[0][0][0], scum[0], tid);
    asm volatile("cp.async.commit_group;" ::: "memory");

    for (int i = 0; i < NTILES; i++) {
        if (i + 1 < NTILES) {
            int nb = (i + 1) % 3;
            ssd_corr_issue(xconv, cumdt, tbase, (i + 1) * TT, h,
                           &sC[nb][0][0], scum[nb], tid);
        }
        asm volatile("cp.async.commit_group;" ::: "memory");
        asm volatile("cp.async.wait_group 1;" ::: "memory");
        __syncthreads();

        int bf = i % 3;
        #pragma unroll
        for (int w = 0; w < TT; w++) {
            float acc = 0.f;
            #pragma unroll
            for (int j4 = 0; j4 < 4; j4++) {
                float4 cv = *(const float4*)&sC[bf][w][q4 + j4 * 16];
                acc = fmaf(cv.x, sin[j4 * 4],     acc);
                acc = fmaf(cv.y, sin[j4 * 4 + 1], acc);
                acc = fmaf(cv.z, sin[j4 * 4 + 2], acc);
                acc = fmaf(cv.w, sin[j4 * 4 + 3], acc);
            }
            acc += __shfl_xor_sync(0xffffffffu, acc, 1);
            acc += __shfl_xor_sync(0xffffffffu, acc, 2);
            if (quad == 0) {
                float wgt = __expf(A * scum[bf][w]);
                y[(size_t)(tbase + i * TT + w) * DINNER + h * DHEAD + p] += wgt * acc;
            }
        }
    }
}

// ---------------- gate + rmsnorm + [hi|lo] split (register-resident) --------
__global__ void gate_norm_split_kernel(const float* __restrict__ zxbcdt,
                                       const float* __restrict__ y,
                                       const float* __restrict__ gw,
                                       __nv_bfloat16* __restrict__ O)
{
    int t = blockIdx.x;
    int tid = threadIdx.x;
    __shared__ float wsum[8];
    const float4* zr = (const float4*)(zxbcdt + (size_t)t * DINPROJ);
    const float4* yr = (const float4*)(y + (size_t)t * DINNER);
    float4 vreg[2];
    float lsum = 0.f;
    #pragma unroll
    for (int it = 0; it < 2; it++) {
        int i4 = tid + it * 256;
        float4 z = zr[i4];
        float4 yv = yr[i4];
        float4 v;
        v.x = yv.x * (z.x / (1.f + __expf(-z.x)));
        v.y = yv.y * (z.y / (1.f + __expf(-z.y)));
        v.z = yv.z * (z.z / (1.f + __expf(-z.z)));
        v.w = yv.w * (z.w / (1.f + __expf(-z.w)));
        vreg[it] = v;
        lsum += v.x * v.x + v.y * v.y + v.z * v.z + v.w * v.w;
    }
    int lane = tid & 31, wid = tid >> 5;
    #pragma unroll
    for (int off = 16; off > 0; off >>= 1)
        lsum += __shfl_xor_sync(0xffffffffu, lsum, off);
    if (lane == 0) wsum[wid] = lsum;
    __syncthreads();
    __shared__ float s_rs;
    if (tid == 0) {
        float tot = 0.f;
        for (int i = 0; i < 8; i++) tot += wsum[i];
        s_rs = rsqrtf(tot / (float)DINNER + EPSV);
    }
    __syncthreads();
    float rs = s_rs;
    __nv_bfloat16* obase = O + (size_t)t * (2 * DINNER);
    #pragma unroll
    for (int it = 0; it < 2; it++) {
        int i4 = tid + it * 256;
        float4 v = vreg[it];
        float4 wv = ((const float4*)gw)[i4];
        float o[4] = {v.x * rs * wv.x, v.y * rs * wv.y, v.z * rs * wv.z, v.w * rs * wv.w};
        __nv_bfloat16 hi[4], lo[4];
        #pragma unroll
        for (int j = 0; j < 4; j++) {
            hi[j] = __float2bfloat16(o[j]);
            lo[j] = __float2bfloat16(o[j] - __bfloat162float(hi[j]));
        }
        __nv_bfloat16* orow = obase + i4 * 4;
        __nv_bfloat162* p0 = (__nv_bfloat162*)orow;
        __nv_bfloat162* p1 = (__nv_bfloat162*)(orow + DINNER);
        p0[0] = __nv_bfloat162{hi[0], hi[1]};  p0[1] = __nv_bfloat162{hi[2], hi[3]};
        p1[0] = __nv_bfloat162{lo[0], lo[1]};  p1[1] = __nv_bfloat162{lo[2], lo[3]};
    }
}

// ---------------- host orchestration ----------------
extern "C" void kernel_launch(void* const* d_in, const int* in_sizes, int n_in,
                              void* d_out, int out_size)
{
    const float* x        = (const float*)d_in[0];
    const float* in_w     = (const float*)d_in[1];
    const float* conv_w   = (const float*)d_in[2];
    const float* conv_b   = (const float*)d_in[3];
    const float* dt_bias  = (const float*)d_in[4];
    const float* A_log    = (const float*)d_in[5];
    const float* Dvec     = (const float*)d_in[6];
    const float* gnorm_w  = (const float*)d_in[7];
    const float* out_w    = (const float*)d_in[8];
    const float* rms_w    = (const float*)d_in[9];
    float* out = (float*)d_out;

    float *p_zx, *p_xc, *p_y, *p_sl, *p_si, *p_cd;
    __nv_bfloat16 *p_as, *p_bwin, *p_bwout;
    cudaGetSymbolAddress((void**)&p_zx, g_zxbcdt);
    cudaGetSymbolAddress((void**)&p_xc, g_xconv);
    cudaGetSymbolAddress((void**)&p_y,  g_y);
    cudaGetSymbolAddress((void**)&p_sl, g_Sloc);
    cudaGetSymbolAddress((void**)&p_si, g_Sin);
    cudaGetSymbolAddress((void**)&p_cd, g_cumdt);
    cudaGetSymbolAddress((void**)&p_as, g_asp);
    cudaGetSymbolAddress((void**)&p_bwin,  g_bw_in);
    cudaGetSymbolAddress((void**)&p_bwout, g_bw_out);

    cudaFuncSetAttribute(gemm_bf16_nt,
                         cudaFuncAttributeMaxDynamicSharedMemorySize, GEMM_SMEM_BYTES);

    cudaMemcpyAsync(out, x, (size_t)TTOT * DMODEL * sizeof(float),
                    cudaMemcpyDeviceToDevice);

    split_w_kernel<<<((size_t)NLAYERS * DINPROJ * DMODEL / 4 + 255) / 256, 256>>>(
        in_w, p_bwin, NLAYERS * DINPROJ, DMODEL);
    split_w_kernel<<<((size_t)NLAYERS * DMODEL * DINNER / 4 + 255) / 256, 256>>>(
        out_w, p_bwout, NLAYERS * DMODEL, DINNER);

    for (int layer = 0; layer < NLAYERS; layer++) {
        const __nv_bfloat16* lw_in_t  = p_bwin  + (size_t)layer * DINPROJ * 2 * DMODEL;
        const __nv_bfloat16* lw_out_t = p_bwout + (size_t)layer * DMODEL * 2 * DINNER;
        const float* lw_cw   = conv_w  + (size_t)layer * CONVDIM * DCONV;
        const float* lw_cb   = conv_b  + (size_t)layer * CONVDIM;
        const float* lw_dtb  = dt_bias + (size_t)layer * NHEADS;
        const float* lw_Alog = A_log   + (size_t)layer * NHEADS;
        const float* lw_D    = Dvec    + (size_t)layer * NHEADS;
        const float* lw_gn   = gnorm_w + (size_t)layer * DINNER;
        const float* lw_rms  = rms_w   + (size_t)layer * DMODEL;

        rmsnorm_split_kernel<<<TTOT, 256>>>(out, lw_rms, p_as);

        {
            dim3 grid((DINPROJ + BN - 1) / BN, TTOT / BM);
            gemm_bf16_nt<<<grid, 256, GEMM_SMEM_BYTES>>>(p_as, lw_in_t, p_zx,
                                                         TTOT, DINPROJ, DMODEL, 0);
        }

        {
            int total = (TTOT / 4) * (CONVDIM / 4);
            conv_silu_kernel<<<(total + 255) / 256, 256>>>(p_zx, lw_cw, lw_cb, p_xc);
        }

        ssd_local_kernel<<<BATCH * NHEADS * NCH, 256>>>(p_xc, p_zx, lw_dtb,
                                                        lw_Alog, lw_D,
                                                        p_y, p_sl, p_cd);
        ssd_combine_kernel<<<BATCH * NHEADS, 256>>>(p_sl, p_cd, lw_Alog, p_si);
        ssd_correct_kernel<<<BATCH * NHEADS * NCH, 256>>>(p_xc, p_cd, lw_Alog, p_si, p_y);

        gate_norm_split_kernel<<<TTOT, 256>>>(p_zx, p_y, lw_gn, p_as);

        {
            dim3 grid(DMODEL / BN, TTOT / BM);
            gemm_bf16_nt<<<grid, 256, GEMM_SMEM_BYTES>>>(p_as, lw_out_t, out,
                                                         TTOT, DMODEL, DINNER, 1);
        }
    }
}